// round 5
// baseline (speedup 1.0000x reference)
#include <cuda_runtime.h>
#include <cuda_bf16.h>

// Problem constants (fixed by the reference)
#define WF 512.0f
#define HF 512.0f
#define NG 2048
#define NPAIR (NG / 2)          // 1024 gaussian pairs
#define HALF_G (NG / 2)         // 1024 gaussians per half
#define HALF_PAIRS (NPAIR / 2)  // 512 pairs per half
#define TPB 224                 // 7 warps/block; 148 blocks = 1 block/SM
#define PXT 4                   // pixels per thread

typedef unsigned long long u64;

__device__ __forceinline__ u64 f2add(u64 a, u64 b) {
    u64 r; asm("add.rn.f32x2 %0,%1,%2;" : "=l"(r) : "l"(a), "l"(b)); return r;
}
__device__ __forceinline__ u64 f2mul(u64 a, u64 b) {
    u64 r; asm("mul.rn.f32x2 %0,%1,%2;" : "=l"(r) : "l"(a), "l"(b)); return r;
}
__device__ __forceinline__ u64 f2fma(u64 a, u64 b, u64 c) {
    u64 r; asm("fma.rn.f32x2 %0,%1,%2,%3;" : "=l"(r) : "l"(a), "l"(b), "l"(c)); return r;
}
__device__ __forceinline__ u64 pk(float lo, float hi) {
    u64 r; asm("mov.b64 %0,{%1,%2};" : "=l"(r) : "f"(lo), "f"(hi)); return r;
}
__device__ __forceinline__ float2 upk(u64 v) {
    float2 o; asm("mov.b64 {%0,%1},%2;" : "=f"(o.x), "=f"(o.y) : "l"(v)); return o;
}
__device__ __forceinline__ float ex2(float x) {
    float r; asm("ex2.approx.ftz.f32 %0,%1;" : "=f"(r) : "f"(x)); return r;
}
__device__ __forceinline__ void redadd(float* p, float v) {
    asm volatile("red.global.add.f32 [%0], %1;" :: "l"(p), "f"(v) : "memory");
}

// ---------------------------------------------------------------------------
// Fused splat kernel. grid = 148 blocks: blockIdx&1 selects the gaussian
// half, blockIdx>>1 selects the pixel tile (74 tiles x 224 threads x 4 px).
//
// Phase 1: block computes its half's coefficients (transcendentals) into smem.
// Phase 2: each thread accumulates 4 pixels over 512 pairs from smem.
// Phase 3: red.global.add into the zero-initialized output (each float gets
//          exactly 2 commutative adds -> deterministic).
//
// Packed per-pair smem layout (16 floats):
// [P0,P1, Q0,Q1, R0,R1, NMX0,NMX1, NMY0,NMY1, CR0,CR1, CG0,CG1, CB0,CB1]
// P,Q,R pre-scaled by -log2(e) so the exponential is a single ex2.
// ---------------------------------------------------------------------------
__global__ void __launch_bounds__(TPB, 1) splat_kernel(const float* __restrict__ x,
                                                       const float* __restrict__ rgb,
                                                       const float* __restrict__ mu,
                                                       const float* __restrict__ scale,
                                                       const float* __restrict__ angle,
                                                       float* __restrict__ out,
                                                       int B) {
    __shared__ float sc[HALF_PAIRS * 16 + 16];  // 32KB + 1 pad pair

    const int h  = blockIdx.x & 1;
    const int tb = blockIdx.x >> 1;

    // ---- Phase 1: per-block coefficient precompute (1024 gaussians) ----
    {
        const float MU_BORDER = 1.05f;
        const float PI_APPROX = 3.1416f;
        const float S_MIN = 1.0f / 30.0f;
        const float S_MAX = 1.0f / 0.75f;
        const float LOG2E = 1.4426950408889634f;

        for (int j = threadIdx.x; j < HALF_G; j += TPB) {
            int gi = h * HALF_G + j;

            float mpx = (tanhf(mu[2 * gi + 0]) * MU_BORDER + 1.0f) * 0.5f * WF;
            float mpy = (tanhf(mu[2 * gi + 1]) * MU_BORDER + 1.0f) * 0.5f * HF;

            float al = tanhf(angle[gi]) * PI_APPROX;
            float c, s;
            sincosf(al, &s, &c);

            float S0 = 1.0f / (1.0f + expf(-scale[2 * gi + 0])) * (S_MAX - S_MIN) + S_MIN;
            float S1 = 1.0f / (1.0f + expf(-scale[2 * gi + 1])) * (S_MAX - S_MIN) + S_MIN;

            float a = S0 * c, b = -S0 * s;
            float e = S1 * s, f = S1 * c;

            float P = -LOG2E * (a * a + e * e);
            float Q = -LOG2E * 2.0f * (a * b + e * f);
            float R = -LOG2E * (b * b + f * f);

            float cr = 1.0f / (1.0f + expf(-rgb[3 * gi + 0]));
            float cg = 1.0f / (1.0f + expf(-rgb[3 * gi + 1]));
            float cb = 1.0f / (1.0f + expf(-rgb[3 * gi + 2]));

            int p = j >> 1;
            int l = j & 1;
            float* base = sc + p * 16;
            base[0 + l]  = P;
            base[2 + l]  = Q;
            base[4 + l]  = R;
            base[6 + l]  = -mpx;
            base[8 + l]  = -mpy;
            base[10 + l] = cr;
            base[12 + l] = cg;
            base[14 + l] = cb;
        }
    }
    __syncthreads();
    if (threadIdx.x < 16) sc[HALF_PAIRS * 16 + threadIdx.x] = sc[threadIdx.x];
    __syncthreads();

    // ---- Phase 2: 4 pixels per thread over 512 pairs ----
    const int t = tb * TPB + threadIdx.x;      // pixel-group index
    const int pix0 = 4 * t;
    const bool valid = (pix0 + 3) < B;         // B is a multiple of 4

    float4 xy01 = make_float4(0.f, 0.f, 0.f, 0.f);
    float4 xy23 = make_float4(0.f, 0.f, 0.f, 0.f);
    if (valid) {
        xy01 = ((const float4*)x)[2 * t];      // pixels 4t, 4t+1
        xy23 = ((const float4*)x)[2 * t + 1];  // pixels 4t+2, 4t+3
    }

    u64 X0 = pk(xy01.x, xy01.x), Y0 = pk(xy01.y, xy01.y);
    u64 X1 = pk(xy01.z, xy01.z), Y1 = pk(xy01.w, xy01.w);
    u64 X2 = pk(xy23.x, xy23.x), Y2 = pk(xy23.y, xy23.y);
    u64 X3 = pk(xy23.z, xy23.z), Y3 = pk(xy23.w, xy23.w);

    u64 R0 = 0ull, G0 = 0ull, B0 = 0ull;
    u64 R1 = 0ull, G1 = 0ull, B1 = 0ull;
    u64 R2 = 0ull, G2 = 0ull, B2 = 0ull;
    u64 R3 = 0ull, G3 = 0ull, B3 = 0ull;

    const ulonglong2* sp = (const ulonglong2*)sc;
    ulonglong2 c0 = sp[0], c1 = sp[1], c2 = sp[2], c3 = sp[3];

#pragma unroll 2
    for (int p = 0; p < HALF_PAIRS; p++) {
        // prefetch next pair's coefficients (pad pair makes last read safe)
        ulonglong2 d0 = sp[4 * p + 4];
        ulonglong2 d1 = sp[4 * p + 5];
        ulonglong2 d2 = sp[4 * p + 6];
        ulonglong2 d3 = sp[4 * p + 7];

#define PIXEL_BODY(Xi, Yi, Ri, Gi, Bi)                                   \
        {                                                                \
            u64 vx = f2add(Xi, c1.y);                                    \
            u64 vy = f2add(Yi, c2.x);                                    \
            u64 t1 = f2fma(c0.y, vy, f2mul(c0.x, vx));                   \
            u64 q  = f2fma(vx, t1, f2mul(f2mul(c1.x, vy), vy));          \
            float2 qq = upk(q);                                          \
            u64 w = pk(ex2(qq.x), ex2(qq.y));                            \
            Ri = f2fma(w, c2.y, Ri);                                     \
            Gi = f2fma(w, c3.x, Gi);                                     \
            Bi = f2fma(w, c3.y, Bi);                                     \
        }

        PIXEL_BODY(X0, Y0, R0, G0, B0)
        PIXEL_BODY(X1, Y1, R1, G1, B1)
        PIXEL_BODY(X2, Y2, R2, G2, B2)
        PIXEL_BODY(X3, Y3, R3, G3, B3)
#undef PIXEL_BODY

        c0 = d0; c1 = d1; c2 = d2; c3 = d3;
    }

    // ---- Phase 3: reduce into output (exactly 2 adds per float) ----
    if (valid) {
        float* o = out + pix0 * 3;   // 12 consecutive floats
#define EMIT(k, Ri, Gi, Bi)                                              \
        {                                                                \
            float2 r = upk(Ri), g = upk(Gi), b = upk(Bi);                \
            redadd(o + 3 * k + 0, r.x + r.y);                            \
            redadd(o + 3 * k + 1, g.x + g.y);                            \
            redadd(o + 3 * k + 2, b.x + b.y);                            \
        }
        EMIT(0, R0, G0, B0)
        EMIT(1, R1, G1, B1)
        EMIT(2, R2, G2, B2)
        EMIT(3, R3, G3, B3)
#undef EMIT
    }
}

// ---------------------------------------------------------------------------
// Launch: inputs in metadata order: x[B,2], rgb[N,3], mu[N,2], scale[N,2], angle[N]
// ---------------------------------------------------------------------------
extern "C" void kernel_launch(void* const* d_in, const int* in_sizes, int n_in,
                              void* d_out, int out_size) {
    const float* x     = (const float*)d_in[0];
    const float* rgb   = (const float*)d_in[1];
    const float* mu    = (const float*)d_in[2];
    const float* scale = (const float*)d_in[3];
    const float* angle = (const float*)d_in[4];
    float* out = (float*)d_out;

    int B = in_sizes[0] / 2;      // 65536

    // zero-init output (graph-capturable async memset), then accumulate
    cudaMemsetAsync(out, 0, (size_t)out_size * sizeof(float));

    // 2 gaussian-halves x ceil(B/(PXT*TPB)) pixel-tiles = 148 blocks
    int pix_blocks = (B + PXT * TPB - 1) / (PXT * TPB);   // 74
    splat_kernel<<<pix_blocks * 2, TPB>>>(x, rgb, mu, scale, angle, out, B);
}

// round 6
// speedup vs baseline: 1.0005x; 1.0005x over previous
#include <cuda_runtime.h>
#include <cuda_bf16.h>

// Problem constants (fixed by the reference)
#define WF 512.0f
#define HF 512.0f
#define NG 2048
#define NSPLIT 4                    // gaussian quarters
#define QG (NG / NSPLIT)            // 512 gaussians per quarter
#define QPAIRS (QG / 2)             // 256 packed pairs per quarter
#define TPB 448                     // 14 warps; 2 blocks/SM -> ~7 warps/SMSP
#define PXT 2                       // pixels per thread
#define PIXTILES 74                 // ceil(65536 / (448*2))
#define BMAX 65536

// Partial images, one per gaussian quarter (non-atomic writes, deterministic)
__device__ float g_partial[NSPLIT][BMAX * 3];

typedef unsigned long long u64;

__device__ __forceinline__ u64 f2add(u64 a, u64 b) {
    u64 r; asm("add.rn.f32x2 %0,%1,%2;" : "=l"(r) : "l"(a), "l"(b)); return r;
}
__device__ __forceinline__ u64 f2mul(u64 a, u64 b) {
    u64 r; asm("mul.rn.f32x2 %0,%1,%2;" : "=l"(r) : "l"(a), "l"(b)); return r;
}
__device__ __forceinline__ u64 f2fma(u64 a, u64 b, u64 c) {
    u64 r; asm("fma.rn.f32x2 %0,%1,%2,%3;" : "=l"(r) : "l"(a), "l"(b), "l"(c)); return r;
}
__device__ __forceinline__ u64 pk(float lo, float hi) {
    u64 r; asm("mov.b64 %0,{%1,%2};" : "=l"(r) : "f"(lo), "f"(hi)); return r;
}
__device__ __forceinline__ float2 upk(u64 v) {
    float2 o; asm("mov.b64 {%0,%1},%2;" : "=f"(o.x), "=f"(o.y) : "l"(v)); return o;
}
__device__ __forceinline__ float ex2(float x) {
    float r; asm("ex2.approx.ftz.f32 %0,%1;" : "=f"(r) : "f"(x)); return r;
}

// ---------------------------------------------------------------------------
// Fused splat kernel. grid = 296 = NSPLIT * PIXTILES (2 blocks/SM exactly).
// block -> (quarter q = b % 4, pixel tile tb = b / 4).
//
// Phase 1: block computes its quarter's 512 gaussian coefficients into smem
//          (tanh/sincos/sigmoid once per gaussian per block).
// Phase 2: each thread accumulates 2 pixels over 256 packed pairs.
// Phase 3: non-atomic store to g_partial[q] (deterministic).
//
// Packed per-pair smem layout (16 floats):
// [P0,P1, Q0,Q1, R0,R1, NMX0,NMX1, NMY0,NMY1, CR0,CR1, CG0,CG1, CB0,CB1]
// P,Q,R pre-scaled by -log2(e) so the exponential is a single ex2.
// ---------------------------------------------------------------------------
__global__ void __launch_bounds__(TPB, 2) splat_kernel(const float* __restrict__ x,
                                                       const float* __restrict__ rgb,
                                                       const float* __restrict__ mu,
                                                       const float* __restrict__ scale,
                                                       const float* __restrict__ angle,
                                                       int B) {
    __shared__ float sc[QPAIRS * 16 + 16];   // 16 KB + 1 pad pair

    const int q  = blockIdx.x & (NSPLIT - 1);
    const int tb = blockIdx.x >> 2;

    // ---- Phase 1: per-block coefficient precompute (512 gaussians) ----
    {
        const float MU_BORDER = 1.05f;
        const float PI_APPROX = 3.1416f;
        const float S_MIN = 1.0f / 30.0f;
        const float S_MAX = 1.0f / 0.75f;
        const float LOG2E = 1.4426950408889634f;

        for (int j = threadIdx.x; j < QG; j += TPB) {
            int gi = q * QG + j;

            float mpx = (tanhf(mu[2 * gi + 0]) * MU_BORDER + 1.0f) * 0.5f * WF;
            float mpy = (tanhf(mu[2 * gi + 1]) * MU_BORDER + 1.0f) * 0.5f * HF;

            float al = tanhf(angle[gi]) * PI_APPROX;
            float c, s;
            sincosf(al, &s, &c);

            float S0 = 1.0f / (1.0f + expf(-scale[2 * gi + 0])) * (S_MAX - S_MIN) + S_MIN;
            float S1 = 1.0f / (1.0f + expf(-scale[2 * gi + 1])) * (S_MAX - S_MIN) + S_MIN;

            float a = S0 * c, b = -S0 * s;
            float e = S1 * s, f = S1 * c;

            float P = -LOG2E * (a * a + e * e);
            float Q = -LOG2E * 2.0f * (a * b + e * f);
            float R = -LOG2E * (b * b + f * f);

            float cr = 1.0f / (1.0f + expf(-rgb[3 * gi + 0]));
            float cg = 1.0f / (1.0f + expf(-rgb[3 * gi + 1]));
            float cb = 1.0f / (1.0f + expf(-rgb[3 * gi + 2]));

            int p = j >> 1;
            int l = j & 1;
            float* base = sc + p * 16;
            base[0 + l]  = P;
            base[2 + l]  = Q;
            base[4 + l]  = R;
            base[6 + l]  = -mpx;
            base[8 + l]  = -mpy;
            base[10 + l] = cr;
            base[12 + l] = cg;
            base[14 + l] = cb;
        }
    }
    __syncthreads();
    if (threadIdx.x < 16) sc[QPAIRS * 16 + threadIdx.x] = sc[threadIdx.x];
    __syncthreads();

    // ---- Phase 2: 2 pixels per thread over 256 pairs ----
    const int t = tb * TPB + threadIdx.x;   // pixel-pair index
    const int pA = 2 * t;
    const bool valid = (pA + 1) < B;

    float4 xy = make_float4(0.f, 0.f, 0.f, 0.f);
    if (valid) xy = ((const float4*)x)[t];   // pixels 2t, 2t+1

    u64 XA = pk(xy.x, xy.x), YA = pk(xy.y, xy.y);
    u64 XB = pk(xy.z, xy.z), YB = pk(xy.w, xy.w);

    u64 aR = 0ull, aG = 0ull, aB = 0ull;
    u64 bR = 0ull, bG = 0ull, bB = 0ull;

    const ulonglong2* sp = (const ulonglong2*)sc;
    ulonglong2 c0 = sp[0], c1 = sp[1], c2 = sp[2], c3 = sp[3];

#pragma unroll 4
    for (int p = 0; p < QPAIRS; p++) {
        // prefetch next pair (pad pair makes last read safe)
        ulonglong2 d0 = sp[4 * p + 4];
        ulonglong2 d1 = sp[4 * p + 5];
        ulonglong2 d2 = sp[4 * p + 6];
        ulonglong2 d3 = sp[4 * p + 7];

        // ---- pixel A ----
        {
            u64 vx = f2add(XA, c1.y);
            u64 vy = f2add(YA, c2.x);
            u64 t1 = f2fma(c0.y, vy, f2mul(c0.x, vx));           // P*vx + Q*vy
            u64 qd = f2fma(vx, t1, f2mul(f2mul(c1.x, vy), vy));  // + R*vy^2
            float2 qq = upk(qd);
            u64 w = pk(ex2(qq.x), ex2(qq.y));
            aR = f2fma(w, c2.y, aR);
            aG = f2fma(w, c3.x, aG);
            aB = f2fma(w, c3.y, aB);
        }
        // ---- pixel B ----
        {
            u64 vx = f2add(XB, c1.y);
            u64 vy = f2add(YB, c2.x);
            u64 t1 = f2fma(c0.y, vy, f2mul(c0.x, vx));
            u64 qd = f2fma(vx, t1, f2mul(f2mul(c1.x, vy), vy));
            float2 qq = upk(qd);
            u64 w = pk(ex2(qq.x), ex2(qq.y));
            bR = f2fma(w, c2.y, bR);
            bG = f2fma(w, c3.x, bG);
            bB = f2fma(w, c3.y, bB);
        }

        c0 = d0; c1 = d1; c2 = d2; c3 = d3;
    }

    // ---- Phase 3: non-atomic partial store (deterministic) ----
    if (valid) {
        float* o = &g_partial[q][pA * 3];   // 6 consecutive floats, 8B aligned
        float2 r0 = upk(aR), g0 = upk(aG), b0 = upk(aB);
        float2 r1 = upk(bR), g1 = upk(bG), b1 = upk(bB);
        ((float2*)o)[0] = make_float2(r0.x + r0.y, g0.x + g0.y);
        ((float2*)o)[1] = make_float2(b0.x + b0.y, r1.x + r1.y);
        ((float2*)o)[2] = make_float2(g1.x + g1.y, b1.x + b1.y);
    }
}

// ---------------------------------------------------------------------------
// Fixed-order tree combine: out = (q0+q1) + (q2+q3). Deterministic.
// ---------------------------------------------------------------------------
__global__ void combine_kernel(float* __restrict__ out, int n4) {
    int i = blockIdx.x * blockDim.x + threadIdx.x;
    if (i < n4) {
        float4 a = ((const float4*)g_partial[0])[i];
        float4 b = ((const float4*)g_partial[1])[i];
        float4 c = ((const float4*)g_partial[2])[i];
        float4 d = ((const float4*)g_partial[3])[i];
        float4 s;
        s.x = (a.x + b.x) + (c.x + d.x);
        s.y = (a.y + b.y) + (c.y + d.y);
        s.z = (a.z + b.z) + (c.z + d.z);
        s.w = (a.w + b.w) + (c.w + d.w);
        ((float4*)out)[i] = s;
    }
}

// ---------------------------------------------------------------------------
// Launch: inputs in metadata order: x[B,2], rgb[N,3], mu[N,2], scale[N,2], angle[N]
// ---------------------------------------------------------------------------
extern "C" void kernel_launch(void* const* d_in, const int* in_sizes, int n_in,
                              void* d_out, int out_size) {
    const float* x     = (const float*)d_in[0];
    const float* rgb   = (const float*)d_in[1];
    const float* mu    = (const float*)d_in[2];
    const float* scale = (const float*)d_in[3];
    const float* angle = (const float*)d_in[4];
    float* out = (float*)d_out;

    int B = in_sizes[0] / 2;      // 65536

    int pix_tiles = (B + PXT * TPB - 1) / (PXT * TPB);     // 74
    splat_kernel<<<pix_tiles * NSPLIT, TPB>>>(x, rgb, mu, scale, angle, B);

    int n4 = (B * 3) / 4;                                   // 49152 float4
    combine_kernel<<<(n4 + 255) / 256, 256>>>(out, n4);
}

// round 7
// speedup vs baseline: 1.4095x; 1.4088x over previous
#include <cuda_runtime.h>
#include <cuda_bf16.h>

// Problem constants (fixed by the reference)
#define WF 512.0f
#define HF 512.0f
#define NGMAX 2048
#define TILES_X 16
#define TILES_Y 16
#define TILES (TILES_X * TILES_Y)
#define TILE_W 32.0f
#define GCAP 2048          // per-tile gaussian list capacity (= NGMAX, cannot overflow)
#define PCAP 2048          // per-tile pixel list capacity (mean 256, Chernoff-safe)
#define GCHUNK 512         // gaussians staged in smem per chunk (16 KB)
#define BMAX 65536

// Per-gaussian coefficients: [P,Q,R,mx,my,cr,cg,cb], P/Q/R pre-scaled by -log2(e)
__device__ float g_coef[NGMAX * 8];
__device__ float g_r2[NGMAX];                  // squared cull radius (pixel units)
__device__ int g_pcnt[TILES];                  // pixels per tile
__device__ int g_gcnt[TILES];                  // gaussians per tile
__device__ int g_plist[TILES * PCAP];          // pixel indices per tile
__device__ unsigned short g_glist[TILES * GCAP]; // gaussian indices per tile (ordered)

__device__ __forceinline__ float ex2(float x) {
    float r; asm("ex2.approx.ftz.f32 %0,%1;" : "=f"(r) : "f"(x)); return r;
}

// ---------------------------------------------------------------------------
// Kernel 1: per-gaussian coefficients + cull radius; also zero pixel counters.
// q(v) = -(d1x^2+d1y^2) = P vx^2 + Q vx vy + R vy^2 (P,Q,R scaled by -log2e).
// |d1|^2 >= min(S0,S1)^2 |v|^2, so |v| > 5/minS  =>  weight < e^-25 (dropped).
// ---------------------------------------------------------------------------
__global__ void precompute_kernel(const float* __restrict__ rgb,
                                  const float* __restrict__ mu,
                                  const float* __restrict__ scale,
                                  const float* __restrict__ angle,
                                  int n) {
    int i = blockIdx.x * blockDim.x + threadIdx.x;
    if (i < TILES) g_pcnt[i] = 0;
    if (i >= n) return;

    const float MU_BORDER = 1.05f;
    const float PI_APPROX = 3.1416f;
    const float S_MIN = 1.0f / 30.0f;
    const float S_MAX = 1.0f / 0.75f;
    const float LOG2E = 1.4426950408889634f;

    float mpx = (tanhf(mu[2 * i + 0]) * MU_BORDER + 1.0f) * 0.5f * WF;
    float mpy = (tanhf(mu[2 * i + 1]) * MU_BORDER + 1.0f) * 0.5f * HF;

    float al = tanhf(angle[i]) * PI_APPROX;
    float c, s;
    sincosf(al, &s, &c);

    float S0 = 1.0f / (1.0f + expf(-scale[2 * i + 0])) * (S_MAX - S_MIN) + S_MIN;
    float S1 = 1.0f / (1.0f + expf(-scale[2 * i + 1])) * (S_MAX - S_MIN) + S_MIN;

    float a = S0 * c, b = -S0 * s;
    float e = S1 * s, f = S1 * c;

    float P = -LOG2E * (a * a + e * e);
    float Q = -LOG2E * 2.0f * (a * b + e * f);
    float R = -LOG2E * (b * b + f * f);

    float cr = 1.0f / (1.0f + expf(-rgb[3 * i + 0]));
    float cg = 1.0f / (1.0f + expf(-rgb[3 * i + 1]));
    float cb = 1.0f / (1.0f + expf(-rgb[3 * i + 2]));

    float Smin = fminf(S0, S1);
    float r = 5.0f / Smin;                 // |d|^2 = 25 level set (w = e^-25)
    g_r2[i] = r * r * 1.0001f + 1e-2f;     // conservative fp margin

    float* base = g_coef + i * 8;
    base[0] = P;  base[1] = Q;  base[2] = R;
    base[3] = mpx; base[4] = mpy;
    base[5] = cr; base[6] = cg; base[7] = cb;
}

// ---------------------------------------------------------------------------
// Kernel 2: (a) bin pixels into tiles (atomic slot; order irrelevant to the
// result since each pixel's sum is over the ordered gaussian list);
// (b) one warp per tile builds the tile's gaussian list IN INDEX ORDER via
// ballot-scan (deterministic).
// Launch: 64 blocks x 256 = 16384 threads (512 warps; first 256 do tiles).
// ---------------------------------------------------------------------------
__global__ void bin_kernel(const float* __restrict__ x, int B) {
    int tid = blockIdx.x * blockDim.x + threadIdx.x;   // 0..16383

    // ---- (a) pixel binning: 4 pixels per thread, coalesced ----
#pragma unroll
    for (int k = 0; k < 4; k++) {
        int pix = tid + k * 16384;
        if (pix < B) {
            float2 xy = ((const float2*)x)[pix];
            int tx = (int)(xy.x * (1.0f / TILE_W));
            int ty = (int)(xy.y * (1.0f / TILE_W));
            tx = min(max(tx, 0), TILES_X - 1);
            ty = min(max(ty, 0), TILES_Y - 1);
            int t = ty * TILES_X + tx;
            int slot = atomicAdd(&g_pcnt[t], 1);
            if (slot < PCAP) g_plist[t * PCAP + slot] = pix;
        }
    }

    // ---- (b) per-tile gaussian scan (1 warp per tile, ordered append) ----
    int w = tid >> 5;
    int lane = tid & 31;
    if (w < TILES) {
        float tx0 = (float)(w & (TILES_X - 1)) * TILE_W;
        float ty0 = (float)(w >> 4) * TILE_W;
        float tx1 = tx0 + TILE_W;
        float ty1 = ty0 + TILE_W;
        int cnt = 0;
        for (int c0 = 0; c0 < NGMAX; c0 += 32) {
            int gi = c0 + lane;
            float mx = g_coef[gi * 8 + 3];
            float my = g_coef[gi * 8 + 4];
            float r2 = g_r2[gi];
            float dx = fmaxf(fmaxf(tx0 - mx, mx - tx1), 0.0f);
            float dy = fmaxf(fmaxf(ty0 - my, my - ty1), 0.0f);
            bool ok = (dx * dx + dy * dy) <= r2;
            unsigned m = __ballot_sync(0xffffffffu, ok);
            if (ok) {
                int pos = cnt + __popc(m & ((1u << lane) - 1u));
                g_glist[w * GCAP + pos] = (unsigned short)gi;
            }
            cnt += __popc(m);
        }
        if (lane == 0) g_gcnt[w] = cnt;
    }
}

// ---------------------------------------------------------------------------
// Kernel 3: per-tile splat. Block t stages its gaussian list's coefficients
// into smem in chunks, then each thread accumulates its pixels (strided over
// the tile's pixel list). Accumulation order = gaussian list order (fixed).
// ---------------------------------------------------------------------------
__global__ void __launch_bounds__(256) splat_tiled(const float* __restrict__ x,
                                                   float* __restrict__ out) {
    __shared__ float sg[GCHUNK * 8];   // 16 KB

    const int t = blockIdx.x;
    const int tid = threadIdx.x;
    const int gcnt = g_gcnt[t];
    const int pcnt = min(g_pcnt[t], PCAP);

    for (int s = 0; s < pcnt; s += 256) {
        int i = s + tid;
        bool valid = i < pcnt;
        float px = 0.f, py = 0.f;
        int pix = 0;
        if (valid) {
            pix = g_plist[t * PCAP + i];
            float2 xy = ((const float2*)x)[pix];
            px = xy.x; py = xy.y;
        }

        float ar = 0.f, ag = 0.f, ab = 0.f;

        for (int c0 = 0; c0 < gcnt; c0 += GCHUNK) {
            int len = min(GCHUNK, gcnt - c0);
            __syncthreads();
            // stage coefficients: 2 float4 per gaussian
            for (int j = tid; j < len * 2; j += 256) {
                int gi = g_glist[t * GCAP + c0 + (j >> 1)];
                ((float4*)sg)[j] = ((const float4*)g_coef)[gi * 2 + (j & 1)];
            }
            __syncthreads();

            if (valid) {
#pragma unroll 2
                for (int j = 0; j < len; j++) {
                    float4 cA = ((const float4*)sg)[j * 2];       // P,Q,R,mx
                    float4 cB = ((const float4*)sg)[j * 2 + 1];   // my,cr,cg,cb
                    float vx = px - cA.w;
                    float vy = py - cB.x;
                    float q = fmaf(vx, fmaf(cA.y, vy, cA.x * vx),
                                   cA.z * vy * vy);
                    float wgt = ex2(q);
                    ar = fmaf(wgt, cB.y, ar);
                    ag = fmaf(wgt, cB.z, ag);
                    ab = fmaf(wgt, cB.w, ab);
                }
            }
        }

        if (valid) {
            out[3 * pix + 0] = ar;
            out[3 * pix + 1] = ag;
            out[3 * pix + 2] = ab;
        }
    }
}

// ---------------------------------------------------------------------------
// Launch: inputs in metadata order: x[B,2], rgb[N,3], mu[N,2], scale[N,2], angle[N]
// ---------------------------------------------------------------------------
extern "C" void kernel_launch(void* const* d_in, const int* in_sizes, int n_in,
                              void* d_out, int out_size) {
    const float* x     = (const float*)d_in[0];
    const float* rgb   = (const float*)d_in[1];
    const float* mu    = (const float*)d_in[2];
    const float* scale = (const float*)d_in[3];
    const float* angle = (const float*)d_in[4];
    float* out = (float*)d_out;

    int N = in_sizes[4];          // 2048
    int B = in_sizes[0] / 2;      // 65536

    precompute_kernel<<<(N + 255) / 256, 256>>>(rgb, mu, scale, angle, N);
    bin_kernel<<<64, 256>>>(x, B);
    splat_tiled<<<TILES, 256>>>(x, out);
}

// round 8
// speedup vs baseline: 1.5882x; 1.1268x over previous
#include <cuda_runtime.h>
#include <cuda_bf16.h>

// Problem constants (fixed by the reference)
#define WF 512.0f
#define HF 512.0f
#define NGMAX 2048
#define TILES_X 16
#define TILES_Y 16
#define TILES (TILES_X * TILES_Y)
#define TILE_W 32.0f
#define PCAP 2048              // per-tile pixel list capacity (mean 256)
#define SEG 512                // gaussians per warp-segment in splat (2048/4)
#define SPLIT 2                // blocks per tile in splat
#define K1_THREADS 16384       // 64 blocks x 256

// Per-gaussian packed coefficients: 2 x float4: [P,Q,R,mx] [my,cr,cg,cb]
// (P,Q,R pre-scaled by -log2(e) so exp is a single ex2)
__device__ float4 g_coef[NGMAX * 2];
// Cull data: [mx, my, r2, 0]
__device__ float4 g_cull[NGMAX];
__device__ int g_pcnt[TILES];
__device__ int g_plist[TILES * PCAP];

__device__ __forceinline__ float ex2(float x) {
    float r; asm("ex2.approx.ftz.f32 %0,%1;" : "=f"(r) : "f"(x)); return r;
}
__device__ __forceinline__ float rcp(float x) {
    float r; asm("rcp.approx.ftz.f32 %0,%1;" : "=f"(r) : "f"(x)); return r;
}
// e^x via ex2
__device__ __forceinline__ float fexp(float x) { return ex2(x * 1.4426950408889634f); }
// tanh(x) = 1 - 2/(e^{2x}+1)
__device__ __forceinline__ float ftanh(float x) {
    float e = ex2(x * 2.8853900817779268f);   // e^{2x}
    return 1.0f - 2.0f * rcp(e + 1.0f);
}
// sigmoid(x) = 1/(1+e^{-x})
__device__ __forceinline__ float fsigm(float x) {
    return rcp(1.0f + fexp(-x));
}

// ---------------------------------------------------------------------------
// Kernel 1 (fused): per-gaussian coefficients + cull radius (threads < N)
// AND pixel->tile binning (all threads, 4 px each). g_pcnt zeroed by a
// graph memset node before this kernel.
// Cull: |d|^2 >= min(S0,S1)^2 |v|^2  =>  |v| > 5/minS gives w < e^-25.
// ---------------------------------------------------------------------------
__global__ void prep_kernel(const float* __restrict__ rgb,
                            const float* __restrict__ mu,
                            const float* __restrict__ scale,
                            const float* __restrict__ angle,
                            const float* __restrict__ x,
                            int N, int B) {
    int tid = blockIdx.x * blockDim.x + threadIdx.x;

    if (tid < N) {
        const float MU_BORDER = 1.05f;
        const float PI_APPROX = 3.1416f;
        const float S_MIN = 1.0f / 30.0f;
        const float S_MAX = 1.0f / 0.75f;
        const float LOG2E = 1.4426950408889634f;
        int i = tid;

        float mpx = (ftanh(mu[2 * i + 0]) * MU_BORDER + 1.0f) * 0.5f * WF;
        float mpy = (ftanh(mu[2 * i + 1]) * MU_BORDER + 1.0f) * 0.5f * HF;

        float al = ftanh(angle[i]) * PI_APPROX;
        float c, s;
        __sincosf(al, &s, &c);

        float S0 = fsigm(scale[2 * i + 0]) * (S_MAX - S_MIN) + S_MIN;
        float S1 = fsigm(scale[2 * i + 1]) * (S_MAX - S_MIN) + S_MIN;

        float a = S0 * c, b = -S0 * s;
        float e = S1 * s, f = S1 * c;

        float P = -LOG2E * (a * a + e * e);
        float Q = -LOG2E * 2.0f * (a * b + e * f);
        float R = -LOG2E * (b * b + f * f);

        float cr = fsigm(rgb[3 * i + 0]);
        float cg = fsigm(rgb[3 * i + 1]);
        float cb = fsigm(rgb[3 * i + 2]);

        float Smin = fminf(S0, S1);
        float r = 5.0f / Smin;                  // w = e^-25 level set
        float r2 = r * r * 1.0001f + 1e-2f;

        g_coef[2 * i]     = make_float4(P, Q, R, mpx);
        g_coef[2 * i + 1] = make_float4(mpy, cr, cg, cb);
        g_cull[i]         = make_float4(mpx, mpy, r2, 0.0f);
    }

    // ---- pixel binning: 4 pixels per thread, coalesced ----
#pragma unroll
    for (int k = 0; k < 4; k++) {
        int pix = tid + k * K1_THREADS;
        if (pix < B) {
            float2 xy = ((const float2*)x)[pix];
            int tx = (int)(xy.x * (1.0f / TILE_W));
            int ty = (int)(xy.y * (1.0f / TILE_W));
            tx = min(max(tx, 0), TILES_X - 1);
            ty = min(max(ty, 0), TILES_Y - 1);
            int t = ty * TILES_X + tx;
            int slot = atomicAdd(&g_pcnt[t], 1);
            if (slot < PCAP) g_plist[t * PCAP + slot] = pix;
        }
    }
}

// ---------------------------------------------------------------------------
// Kernel 2: per-tile splat with in-block gaussian cull.
// grid = TILES*SPLIT blocks x 128 threads. Block (t, sub): warp w ballot-
// compacts its contiguous 512-gaussian segment (index order preserved) into
// smem; threads then accumulate pixels sub::SPLIT of the tile's list over
// segments 0..3 in order (fixed accumulation order -> deterministic).
// Coefficient reads are warp-uniform LDG.128 (L1-resident 64KB table).
// ---------------------------------------------------------------------------
__global__ void __launch_bounds__(128) splat_tiled(const float* __restrict__ x,
                                                   float* __restrict__ out) {
    __shared__ unsigned short slist[4][SEG];
    __shared__ int scnt[4];

    const int t   = blockIdx.x >> 1;       // tile (SPLIT=2)
    const int sub = blockIdx.x & 1;
    const int tid = threadIdx.x;
    const int w   = tid >> 5;
    const int lane = tid & 31;

    const float tx0 = (float)(t & (TILES_X - 1)) * TILE_W;
    const float ty0 = (float)(t >> 4) * TILE_W;
    const float tx1 = tx0 + TILE_W;
    const float ty1 = ty0 + TILE_W;

    // ---- in-block cull scan: warp w covers [w*SEG, (w+1)*SEG) ----
    {
        int cnt = 0;
        for (int c0 = w * SEG; c0 < (w + 1) * SEG; c0 += 32) {
            int gi = c0 + lane;
            float4 cu = g_cull[gi];
            float dx = fmaxf(fmaxf(tx0 - cu.x, cu.x - tx1), 0.0f);
            float dy = fmaxf(fmaxf(ty0 - cu.y, cu.y - ty1), 0.0f);
            bool ok = (dx * dx + dy * dy) <= cu.z;
            unsigned m = __ballot_sync(0xffffffffu, ok);
            if (ok) {
                int pos = cnt + __popc(m & ((1u << lane) - 1u));
                slist[w][pos] = (unsigned short)gi;
            }
            cnt += __popc(m);
        }
        if (lane == 0) scnt[w] = cnt;
    }
    __syncthreads();

    const int n0 = scnt[0], n1 = scnt[1], n2 = scnt[2], n3 = scnt[3];
    const int pcnt = min(g_pcnt[t], PCAP);

    // ---- pixels sub::SPLIT of this tile's list ----
    for (int i = SPLIT * tid + sub; i < pcnt; i += SPLIT * 128) {
        int pix = g_plist[t * PCAP + i];
        float2 xy = ((const float2*)x)[pix];
        float px = xy.x, py = xy.y;

        float ar = 0.f, ag = 0.f, ab = 0.f;

#pragma unroll
        for (int seg = 0; seg < 4; seg++) {
            int n = (seg == 0) ? n0 : (seg == 1) ? n1 : (seg == 2) ? n2 : n3;
#pragma unroll 2
            for (int j = 0; j < n; j++) {
                int gi = slist[seg][j];
                float4 cA = g_coef[2 * gi];       // P,Q,R,mx
                float4 cB = g_coef[2 * gi + 1];   // my,cr,cg,cb
                float vx = px - cA.w;
                float vy = py - cB.x;
                float q = fmaf(vx, fmaf(cA.y, vy, cA.x * vx), cA.z * vy * vy);
                float wgt = ex2(q);
                ar = fmaf(wgt, cB.y, ar);
                ag = fmaf(wgt, cB.z, ag);
                ab = fmaf(wgt, cB.w, ab);
            }
        }

        out[3 * pix + 0] = ar;
        out[3 * pix + 1] = ag;
        out[3 * pix + 2] = ab;
    }
}

// ---------------------------------------------------------------------------
// Launch: inputs in metadata order: x[B,2], rgb[N,3], mu[N,2], scale[N,2], angle[N]
// ---------------------------------------------------------------------------
extern "C" void kernel_launch(void* const* d_in, const int* in_sizes, int n_in,
                              void* d_out, int out_size) {
    const float* x     = (const float*)d_in[0];
    const float* rgb   = (const float*)d_in[1];
    const float* mu    = (const float*)d_in[2];
    const float* scale = (const float*)d_in[3];
    const float* angle = (const float*)d_in[4];
    float* out = (float*)d_out;

    int N = in_sizes[4];          // 2048
    int B = in_sizes[0] / 2;      // 65536

    // zero the per-tile pixel counters (graph memset node; no allocation)
    void* pcnt_addr = nullptr;
    cudaGetSymbolAddress(&pcnt_addr, g_pcnt);
    cudaMemsetAsync(pcnt_addr, 0, TILES * sizeof(int));

    prep_kernel<<<K1_THREADS / 256, 256>>>(rgb, mu, scale, angle, x, N, B);
    splat_tiled<<<TILES * SPLIT, 128>>>(x, out);
}

// round 9
// speedup vs baseline: 1.9736x; 1.2427x over previous
#include <cuda_runtime.h>
#include <cuda_bf16.h>

// Problem constants (fixed by the reference)
#define WF 512.0f
#define HF 512.0f
#define NGMAX 2048
#define TILES_X 16
#define TILES_Y 16
#define TILES (TILES_X * TILES_Y)
#define TILE_W 32.0f
#define PCAP 2048              // per-tile pixel list capacity (mean 256)
#define SEG 512                // gaussians per warp-segment (2048/4)
#define SEGCAP 256             // staged coefficients per segment (overflow -> global)
#define SPLIT 2                // blocks per tile in splat
#define K1_THREADS 16384       // 64 blocks x 256

// Per-gaussian packed coefficients: 2 x float4: [P,Q,R,mx] [my,cr,cg,cb]
// (P,Q,R pre-scaled by -log2(e) so exp is a single ex2)
__device__ float4 g_coef[NGMAX * 2];
// Cull data: [mx, my, r2, 0]
__device__ float4 g_cull[NGMAX];
__device__ int g_pcnt[TILES];
__device__ int g_pidx[TILES * PCAP];     // pixel index per slot
__device__ float2 g_pxy[TILES * PCAP];   // pixel coords per slot (coalesced read)

__device__ __forceinline__ float ex2(float x) {
    float r; asm("ex2.approx.ftz.f32 %0,%1;" : "=f"(r) : "f"(x)); return r;
}
__device__ __forceinline__ float rcp(float x) {
    float r; asm("rcp.approx.ftz.f32 %0,%1;" : "=f"(r) : "f"(x)); return r;
}
__device__ __forceinline__ float fexp(float x) { return ex2(x * 1.4426950408889634f); }
__device__ __forceinline__ float ftanh(float x) {
    float e = ex2(x * 2.8853900817779268f);   // e^{2x}
    return 1.0f - 2.0f * rcp(e + 1.0f);
}
__device__ __forceinline__ float fsigm(float x) {
    return rcp(1.0f + fexp(-x));
}

// ---------------------------------------------------------------------------
// Kernel 1 (fused): per-gaussian coefficients + cull radius (threads < N)
// AND pixel->tile binning (all threads, 4 px each; stores coords + index so
// the splat reads its pixel list coalesced). g_pcnt zeroed by a memset node.
// Cull: |d|^2 >= min(S0,S1)^2 |v|^2  =>  |v| > 5/minS gives w < e^-25.
// ---------------------------------------------------------------------------
__global__ void prep_kernel(const float* __restrict__ rgb,
                            const float* __restrict__ mu,
                            const float* __restrict__ scale,
                            const float* __restrict__ angle,
                            const float* __restrict__ x,
                            int N, int B) {
    int tid = blockIdx.x * blockDim.x + threadIdx.x;

    if (tid < N) {
        const float MU_BORDER = 1.05f;
        const float PI_APPROX = 3.1416f;
        const float S_MIN = 1.0f / 30.0f;
        const float S_MAX = 1.0f / 0.75f;
        const float LOG2E = 1.4426950408889634f;
        int i = tid;

        float mpx = (ftanh(mu[2 * i + 0]) * MU_BORDER + 1.0f) * 0.5f * WF;
        float mpy = (ftanh(mu[2 * i + 1]) * MU_BORDER + 1.0f) * 0.5f * HF;

        float al = ftanh(angle[i]) * PI_APPROX;
        float c, s;
        __sincosf(al, &s, &c);

        float S0 = fsigm(scale[2 * i + 0]) * (S_MAX - S_MIN) + S_MIN;
        float S1 = fsigm(scale[2 * i + 1]) * (S_MAX - S_MIN) + S_MIN;

        float a = S0 * c, b = -S0 * s;
        float e = S1 * s, f = S1 * c;

        float P = -LOG2E * (a * a + e * e);
        float Q = -LOG2E * 2.0f * (a * b + e * f);
        float R = -LOG2E * (b * b + f * f);

        float cr = fsigm(rgb[3 * i + 0]);
        float cg = fsigm(rgb[3 * i + 1]);
        float cb = fsigm(rgb[3 * i + 2]);

        float Smin = fminf(S0, S1);
        float r = 5.0f / Smin;                  // w = e^-25 level set
        float r2 = r * r * 1.0001f + 1e-2f;

        g_coef[2 * i]     = make_float4(P, Q, R, mpx);
        g_coef[2 * i + 1] = make_float4(mpy, cr, cg, cb);
        g_cull[i]         = make_float4(mpx, mpy, r2, 0.0f);
    }

    // ---- pixel binning: 4 pixels per thread, coalesced reads ----
#pragma unroll
    for (int k = 0; k < 4; k++) {
        int pix = tid + k * K1_THREADS;
        if (pix < B) {
            float2 xy = ((const float2*)x)[pix];
            int tx = (int)(xy.x * (1.0f / TILE_W));
            int ty = (int)(xy.y * (1.0f / TILE_W));
            tx = min(max(tx, 0), TILES_X - 1);
            ty = min(max(ty, 0), TILES_Y - 1);
            int t = ty * TILES_X + tx;
            int slot = atomicAdd(&g_pcnt[t], 1);
            if (slot < PCAP) {
                g_pidx[t * PCAP + slot] = pix;
                g_pxy[t * PCAP + slot] = xy;
            }
        }
    }
}

// ---------------------------------------------------------------------------
// Kernel 2: per-tile splat. During the cull scan each warp stages the
// COMPACTED COEFFICIENTS of its 512-gaussian segment into smem (index order
// preserved). Inner loop is then pure LDS + FMA + ex2 (no gather). Segments
// processed in fixed order 0..3 -> deterministic accumulation per pixel.
// Rare >SEGCAP overflow falls back to global reads via the index list.
// ---------------------------------------------------------------------------
__global__ void __launch_bounds__(128) splat_tiled(float* __restrict__ out) {
    __shared__ float4 scoef[4][SEGCAP][2];      // 32 KB staged coefficients
    __shared__ unsigned short slist[4][SEG];    // 4 KB index list (overflow path)
    __shared__ int scnt[4];

    const int t   = blockIdx.x >> 1;       // tile (SPLIT=2)
    const int sub = blockIdx.x & 1;
    const int tid = threadIdx.x;
    const int w   = tid >> 5;
    const int lane = tid & 31;

    const float tx0 = (float)(t & (TILES_X - 1)) * TILE_W;
    const float ty0 = (float)(t >> 4) * TILE_W;
    const float tx1 = tx0 + TILE_W;
    const float ty1 = ty0 + TILE_W;

    // ---- cull scan + coefficient staging: warp w covers [w*SEG,(w+1)*SEG) ----
    {
        int cnt = 0;
        for (int c0 = w * SEG; c0 < (w + 1) * SEG; c0 += 32) {
            int gi = c0 + lane;
            float4 cu = g_cull[gi];
            float dx = fmaxf(fmaxf(tx0 - cu.x, cu.x - tx1), 0.0f);
            float dy = fmaxf(fmaxf(ty0 - cu.y, cu.y - ty1), 0.0f);
            bool ok = (dx * dx + dy * dy) <= cu.z;
            unsigned m = __ballot_sync(0xffffffffu, ok);
            if (ok) {
                int pos = cnt + __popc(m & ((1u << lane) - 1u));
                slist[w][pos] = (unsigned short)gi;
                if (pos < SEGCAP) {
                    scoef[w][pos][0] = g_coef[2 * gi];
                    scoef[w][pos][1] = g_coef[2 * gi + 1];
                }
            }
            cnt += __popc(m);
        }
        if (lane == 0) scnt[w] = cnt;
    }
    __syncthreads();

    const int pcnt = min(g_pcnt[t], PCAP);

    // ---- pixels sub::SPLIT of this tile's list (coalesced coords) ----
    for (int i = SPLIT * tid + sub; i < pcnt; i += SPLIT * 128) {
        float2 xy = g_pxy[t * PCAP + i];
        float px = xy.x, py = xy.y;

        float ar = 0.f, ag = 0.f, ab = 0.f;

#pragma unroll
        for (int seg = 0; seg < 4; seg++) {
            int n = scnt[seg];
            int nc = min(n, SEGCAP);
            // fast path: staged coefficients (LDS broadcast, prefetchable)
#pragma unroll 4
            for (int j = 0; j < nc; j++) {
                float4 cA = scoef[seg][j][0];     // P,Q,R,mx
                float4 cB = scoef[seg][j][1];     // my,cr,cg,cb
                float vx = px - cA.w;
                float vy = py - cB.x;
                float q = fmaf(vx, fmaf(cA.y, vy, cA.x * vx), (cA.z * vy) * vy);
                float wgt = ex2(q);
                ar = fmaf(wgt, cB.y, ar);
                ag = fmaf(wgt, cB.z, ag);
                ab = fmaf(wgt, cB.w, ab);
            }
            // overflow path (effectively never taken; preserves correctness)
            for (int j = SEGCAP; j < n; j++) {
                int gi = slist[seg][j];
                float4 cA = g_coef[2 * gi];
                float4 cB = g_coef[2 * gi + 1];
                float vx = px - cA.w;
                float vy = py - cB.x;
                float q = fmaf(vx, fmaf(cA.y, vy, cA.x * vx), (cA.z * vy) * vy);
                float wgt = ex2(q);
                ar = fmaf(wgt, cB.y, ar);
                ag = fmaf(wgt, cB.z, ag);
                ab = fmaf(wgt, cB.w, ab);
            }
        }

        int pix = g_pidx[t * PCAP + i];
        out[3 * pix + 0] = ar;
        out[3 * pix + 1] = ag;
        out[3 * pix + 2] = ab;
    }
}

// ---------------------------------------------------------------------------
// Launch: inputs in metadata order: x[B,2], rgb[N,3], mu[N,2], scale[N,2], angle[N]
// ---------------------------------------------------------------------------
extern "C" void kernel_launch(void* const* d_in, const int* in_sizes, int n_in,
                              void* d_out, int out_size) {
    const float* x     = (const float*)d_in[0];
    const float* rgb   = (const float*)d_in[1];
    const float* mu    = (const float*)d_in[2];
    const float* scale = (const float*)d_in[3];
    const float* angle = (const float*)d_in[4];
    float* out = (float*)d_out;

    int N = in_sizes[4];          // 2048
    int B = in_sizes[0] / 2;      // 65536

    // zero the per-tile pixel counters (graph memset node; no allocation)
    void* pcnt_addr = nullptr;
    cudaGetSymbolAddress(&pcnt_addr, g_pcnt);
    cudaMemsetAsync(pcnt_addr, 0, TILES * sizeof(int));

    prep_kernel<<<K1_THREADS / 256, 256>>>(rgb, mu, scale, angle, x, N, B);
    splat_tiled<<<TILES * SPLIT, 128>>>(out);
}